// round 13
// baseline (speedup 1.0000x reference)
#include <cuda_runtime.h>
#include <math.h>

#define NBOX 4096
#define WORDS 128   // NBOX/32
#define MM 20
#define HH 16
#define NLAB 4

// ---------------- device scratch ----------------
__device__ int            g_rankpart[2 * NBOX];
__device__ float          g_boxes7[NBOX * 7];
__device__ float4         g_bev4[NBOX];
__device__ int            g_lab[NBOX];
__device__ unsigned int   g_sup0[WORDS];              // invalid bits
__device__ unsigned int   g_labmask[NLAB * WORDS];
__device__ unsigned int   g_rows[NBOX * WORDS];       // only deg>31 rows valid
__device__ unsigned short g_pool[NBOX * 31];          // upper (j>i) neighbor lists, ascending
__device__ unsigned int   g_ofsdeg[NBOX];             // ofs(24) | min(deg,255)(8)
__device__ unsigned int   g_poolcnt;
__device__ unsigned short g_lolist4[NBOX * 4];        // first 4 reverse neighbors
__device__ unsigned short g_lolist[NBOX * 64];        // reverse overflow (pos 4..63)
__device__ int            g_deglo[NBOX];
__device__ int            g_suppr[NBOX];              // min kept smaller neighbor, -1 none
__device__ unsigned int   g_keep[WORDS];
__device__ int            g_mtask[NBOX];
__device__ int            g_nmt;

__device__ __forceinline__ unsigned sort_key(float sc) {
    float f = (sc > 0.2f) ? sc : __int_as_float(0xff800000);
    unsigned b = __float_as_uint(f);
    unsigned u = (b & 0x80000000u) ? ~b : (b | 0x80000000u);
    return ~u;   // ascending == score descending
}

__device__ __forceinline__ float iou_of(float4 a, float aa, float4 bb) {
    float xmin = fmaxf(a.x, bb.x), ymin = fmaxf(a.y, bb.y);
    float xmax = fminf(a.z, bb.z), ymax = fminf(a.w, bb.w);
    float inter = fmaxf(xmax - xmin, 0.f) * fmaxf(ymax - ymin, 0.f);
    float ab = (bb.z - bb.x) * (bb.w - bb.y);
    return inter / fmaxf(aa + ab - inter, 1e-6f);
}

// ---------------- kernel 1: split-j rank sort + global zero-init ----------------
__global__ void k_rank(const float* __restrict__ scores) {
    __shared__ unsigned sk[NBOX / 2];
    int t = threadIdx.x;
    int gid = blockIdx.x * 128 + t;          // 0..8191
    if (gid < NBOX) g_deglo[gid] = 0;
    if (gid < WORDS) g_sup0[gid] = 0;
    if (gid < NLAB * WORDS) g_labmask[gid] = 0;
    if (gid == 0) { g_poolcnt = 0; g_nmt = 0; }

    int half = blockIdx.x >> 5;              // 0 or 1
    int jo = half * (NBOX / 2);
    for (int k = t; k < NBOX / 2; k += 128) sk[k] = sort_key(scores[jo + k]);
    __syncthreads();
    int i = (blockIdx.x & 31) * 128 + t;
    unsigned ki = sort_key(scores[i]);
    int rank = 0;
    const uint4* sk4 = (const uint4*)sk;
#pragma unroll 4
    for (int j4 = 0; j4 < NBOX / 8; j4++) {
        uint4 v = sk4[j4];
        int j = jo + j4 * 4;
        rank += (v.x < ki) || (v.x == ki && j + 0 < i);
        rank += (v.y < ki) || (v.y == ki && j + 1 < i);
        rank += (v.z < ki) || (v.z == ki && j + 2 < i);
        rank += (v.w < ki) || (v.w == ki && j + 3 < i);
    }
    g_rankpart[half * NBOX + i] = rank;
}

// ---------------- kernel 2: scatter gather, BEV, label masks, prefill ----------------
__global__ void k_prep(const float* __restrict__ pb, const float* __restrict__ ps,
                       const int* __restrict__ pl, float* __restrict__ out) {
    int o = blockIdx.x * blockDim.x + threadIdx.x;   // original index
    int s = g_rankpart[o] + g_rankpart[NBOX + o];    // sorted position
    float b0 = pb[o*9+0], b1 = pb[o*9+1], b2 = pb[o*9+2];
    float b3 = pb[o*9+3], b4 = pb[o*9+4], b5 = pb[o*9+5];
    float b6 = pb[o*9+6], b7 = pb[o*9+7], b8 = pb[o*9+8];
    g_boxes7[s*7+0] = b0; g_boxes7[s*7+1] = b1; g_boxes7[s*7+2] = b2;
    g_boxes7[s*7+3] = b3; g_boxes7[s*7+4] = b4; g_boxes7[s*7+5] = b5;
    g_boxes7[s*7+6] = b6;
    out[s*9+0] = b0; out[s*9+1] = b1; out[s*9+2] = b2;
    out[s*9+3] = b3; out[s*9+4] = b4; out[s*9+5] = b5;
    out[s*9+6] = b6; out[s*9+7] = b7; out[s*9+8] = b8;

    const float PI = 3.14159265358979323846f;
    float ang = b6 - floorf(b6 / PI + 0.5f) * PI;
    bool sw = fabsf(ang) >= 0.25f * PI;
    float dx = sw ? b4 : b3;
    float dy = sw ? b3 : b4;
    g_bev4[s] = make_float4(b0 - dx * 0.5f, b1 - dy * 0.5f, b0 + dx * 0.5f, b1 + dy * 0.5f);

    int lab = pl[o];
    g_lab[s] = lab;
    float sc = ps[o];
    out[NBOX*9  + s] = sc;
    out[NBOX*10 + s] = (float)lab;

    if (!(sc > 0.2f)) atomicOr(&g_sup0[s >> 5], 1u << (s & 31));
    atomicOr(&g_labmask[lab * WORDS + (s >> 5)], 1u << (s & 31));
}

// ---------------- kernel 3: adjacency + upper lists + reverse appends ----------------
__global__ void __launch_bounds__(1024) k_adj() {
    __shared__ float4 sb[1024];
    __shared__ float  sa[1024];
    __shared__ float4 rb[32];
    __shared__ int    rl[32];
    int t = threadIdx.x;
    int R = blockIdx.x * 32;
    if (t < 32) { rb[t] = g_bev4[R + t]; rl[t] = g_lab[R + t]; }
    __syncthreads();
    int rloc = t >> 5;
    int r = R + rloc;
    int wl = t & 31;
    float4 a = rb[rloc];
    int la = rl[rloc];
    float aa = (a.z - a.x) * (a.w - a.y);
    int w0 = blockIdx.x;
    int T0 = w0 >> 5;

    unsigned mw[4] = {0, 0, 0, 0};
#pragma unroll
    for (int T = 0; T < 4; T++) {
        if (T >= T0) {
            float4 bb0 = g_bev4[T * 1024 + t];
            sb[t] = bb0;
            sa[t] = (bb0.z - bb0.x) * (bb0.w - bb0.y);
            __syncthreads();
            int w = T * 32 + wl;
            unsigned m = 0;
            if (w >= w0) {
                unsigned cand = g_labmask[la * WORDS + w];
                if (w == w0) cand &= 0xffffffffu << (r & 31);
                while (cand) {
                    int b = __ffs(cand) - 1; cand &= cand - 1;
                    int jj = wl * 32 + b;
                    if (iou_of(a, aa, sb[jj]) > 0.3f) m |= 1u << b;
                }
            }
            mw[T] = m;
            __syncthreads();
        }
    }

    int excl[4], tbase[4];
    int running = 0;
#pragma unroll
    for (int T = 0; T < 4; T++) {
        int pc = __popc(mw[T]);
        int incl = pc;
        for (int d = 1; d < 32; d <<= 1) {
            int n = __shfl_up_sync(0xffffffffu, incl, d);
            if (wl >= d) incl += n;
        }
        excl[T] = incl - pc;
        tbase[T] = running;
        running += __shfl_sync(0xffffffffu, incl, 31);
    }
    int deg = running - 1;            // diag always set
    int cap = deg < 31 ? deg : 31;

    unsigned base = 0;
    if (wl == 0 && deg > 0) base = atomicAdd(&g_poolcnt, (unsigned)cap);
    base = __shfl_sync(0xffffffffu, base, 0);

#pragma unroll
    for (int T = 0; T < 4; T++) {
        unsigned v = mw[T];
        int rank0 = tbase[T] + excl[T];   // diag is rank 0
        int wword = T * 32 + wl;
        while (v) {
            int b = __ffs(v) - 1; v &= v - 1;
            int j = wword * 32 + b;
            if (rank0 > 0) {
                if (rank0 - 1 < 31)
                    g_pool[base + rank0 - 1] = (unsigned short)j;
                int pos = atomicAdd(&g_deglo[j], 1);     // reverse edge j <- r
                if (pos < 4) g_lolist4[j * 4 + pos] = (unsigned short)r;
                else if (pos < 64) g_lolist[j * 64 + pos] = (unsigned short)r;
            }
            rank0++;
        }
    }
    if (wl == 0)
        g_ofsdeg[r] = base | ((unsigned)(deg > 255 ? 255 : deg) << 24);

    if (deg > 31) {
        g_rows[r * WORDS +       wl] = mw[0];
        g_rows[r * WORDS +  32 + wl] = mw[1];
        g_rows[r * WORDS +  64 + wl] = mw[2];
        g_rows[r * WORDS +  96 + wl] = mw[3];
    }
}

// ---------------- kernel 4: word-owner Gauss-Seidel fixpoint (128 threads) ----------------
__global__ void __launch_bounds__(128) k_fix() {
    __shared__ unsigned char status[NBOX];      // 0 unknown, 1 kept, 2 not-kept
    __shared__ unsigned char sdeglo[NBOX];
    __shared__ unsigned short slo4[NBOX * 4];   // 32 KB inline reverse lists
    __shared__ int s_changed;
    int t = threadIdx.x;                        // thread t owns word t

    for (int k = t; k < NBOX; k += 128) {
        int n = g_deglo[k];
        sdeglo[k] = (unsigned char)(n > 255 ? 255 : n);
    }
    for (int k = t; k < NBOX / 2; k += 128)     // 2048 uint4 = 32 KB
        ((uint4*)slo4)[k] = ((const uint4*)g_lolist4)[k];
    unsigned valid_w = ~g_sup0[t];
    {
        unsigned v = valid_w;
#pragma unroll 8
        for (int b = 0; b < 32; b++)
            status[t * 32 + b] = ((v >> b) & 1u) ? 0 : 2;
    }
    __syncthreads();

    unsigned unres = valid_w;                   // register-resident unresolved mask
    for (int it = 0; it < NBOX && __syncthreads_or(unres != 0); it++) {
        if (t == 0) s_changed = 0;
        __syncthreads();
        int ch = 0;
        unsigned rem = unres;
        while (rem) {
            int b = __ffs(rem) - 1;
            unsigned bit = 1u << b;
            int j = t * 32 + b;
            int n = sdeglo[j];
            int st;
            if (n <= 64) {
                bool anyK = false, allR = true;
                for (int k = 0; k < n; k++) {
                    int u = (k < 4) ? slo4[j * 4 + k] : g_lolist[j * 64 + k];
                    unsigned char s = status[u];
                    anyK |= (s == 1); allR &= (s != 0);
                }
                st = anyK ? 2 : (allR ? 1 : 0);
            } else {
                float4 a = g_bev4[j]; int la = g_lab[j];
                float aa = (a.z - a.x) * (a.w - a.y);
                bool anyK = false, allR = true;
                for (int k = 0; k < j; k++) {
                    if (g_lab[k] != la) continue;
                    if (iou_of(a, aa, g_bev4[k]) > 0.3f) {
                        unsigned char s = status[k];
                        anyK |= (s == 1); allR &= (s != 0);
                    }
                }
                st = anyK ? 2 : (allR ? 1 : 0);
            }
            if (st) { status[j] = (unsigned char)st; unres &= ~bit; ch = 1; }
            rem &= ~bit;
        }
        if (ch) s_changed = 1;
        __syncthreads();
        if (!s_changed) break;        // no progress anywhere -> done (shouldn't happen)
        __syncthreads();
    }
    __syncthreads();

    // suppressor + keep + merge-task compaction (word-owner)
    unsigned kw = 0;
    unsigned v = valid_w;
    for (int b = 0; b < 32; b++) {
        int j = t * 32 + b;
        unsigned char stj = status[j];
        int sup = -1;
        if (stj == 2 && ((v >> b) & 1u)) {
            int n = sdeglo[j];
            int mn = 0x7fffffff;
            if (n <= 64) {
                for (int k = 0; k < n; k++) {
                    int u = (k < 4) ? slo4[j * 4 + k] : g_lolist[j * 64 + k];
                    if (status[u] == 1 && u < mn) mn = u;
                }
            } else {
                float4 a = g_bev4[j]; int la = g_lab[j];
                float aa = (a.z - a.x) * (a.w - a.y);
                for (int k = 0; k < j; k++) {
                    if (g_lab[k] != la || status[k] != 1) continue;
                    if (iou_of(a, aa, g_bev4[k]) > 0.3f) { mn = k; break; }
                }
            }
            sup = mn;
        }
        g_suppr[j] = sup;
        if (stj == 1) {
            kw |= 1u << b;
            if ((g_ofsdeg[j] >> 24) > 0)
                g_mtask[atomicAdd(&g_nmt, 1)] = j;
        }
    }
    g_keep[t] = kw;
}

// ---------------- kernel 5: parallel merge MLP + keep flags ----------------
__global__ void __launch_bounds__(128) k_merge(
    const float* __restrict__ w1, const float* __restrict__ b1,
    const float* __restrict__ w2, const float* __restrict__ b2,
    const float* __restrict__ w3, const float* __restrict__ b3,
    float* __restrict__ out) {
    __shared__ float ob[140];
    __shared__ float h1[112], h2[112];
    __shared__ float sw1[320], sw2[256], sw3[16], sb1v[16], sb2v[16];
    __shared__ float sb3v;
    __shared__ int scand[20];
    __shared__ int s_cnt;
    int t = threadIdx.x;

    if (blockIdx.x < 32) {
        int s = blockIdx.x * 128 + t;
        out[NBOX * 11 + s] = ((g_keep[s >> 5] >> (s & 31)) & 1u) ? 1.0f : 0.0f;
    }

    for (int k = t; k < 320; k += 128) sw1[k] = w1[k];
    for (int k = t; k < 256; k += 128) sw2[k] = w2[k];
    if (t < 16) { sw3[t] = w3[t]; sb1v[t] = b1[t]; sb2v[t] = b2[t]; }
    if (t == 0) sb3v = b3[0];
    __syncthreads();

    int nm = g_nmt;
    for (int task = blockIdx.x; task < nm; task += gridDim.x) {
        int i = g_mtask[task];
        unsigned od = g_ofsdeg[i];
        int deg = od >> 24;

        if (t < 32) {
            if (deg <= 31) {
                bool sel = false; int j = 0;
                if (t < deg) {
                    j = (int)g_pool[(od & 0xffffff) + t];
                    sel = (g_suppr[j] == i);
                }
                unsigned m = __ballot_sync(0xffffffffu, sel);
                if (t == 0) { s_cnt = __popc(m) + 1; scand[0] = i; }
                if (sel) {
                    int rk = __popc(m & ((1u << t) - 1u));
                    if (rk < 19) scand[1 + rk] = j;
                }
            } else {
                uint4 rv = ((const uint4*)(g_rows + (size_t)i * WORDS))[t];
                int ww0 = i >> 5;
                unsigned mm[4];
#pragma unroll
                for (int q = 0; q < 4; q++) {
                    int w = t * 4 + q;
                    unsigned v = (q == 0) ? rv.x : (q == 1) ? rv.y : (q == 2) ? rv.z : rv.w;
                    if (w < ww0) v = 0;
                    if (w == ww0) v &= (0xfffffffeu << (i & 31));   // strictly > i
                    unsigned sel = 0;
                    while (v) {
                        int b = __ffs(v) - 1; v &= v - 1;
                        if (g_suppr[w * 32 + b] == i) sel |= 1u << b;
                    }
                    mm[q] = sel;
                }
                int pc = __popc(mm[0]) + __popc(mm[1]) + __popc(mm[2]) + __popc(mm[3]);
                int incl = pc;
                for (int d = 1; d < 32; d <<= 1) {
                    int v = __shfl_up_sync(0xffffffffu, incl, d);
                    if (t >= d) incl += v;
                }
                int total = __shfl_sync(0xffffffffu, incl, 31);
                int start = incl - pc;
#pragma unroll
                for (int q = 0; q < 4; q++) {
                    unsigned v = mm[q];
                    while (v) {
                        int b = __ffs(v) - 1; v &= v - 1;
                        if (start < 19) scand[1 + start] = (t * 4 + q) * 32 + b;
                        start++;
                    }
                }
                if (t == 0) { s_cnt = total + 1; scand[0] = i; }
            }
        }
        __syncthreads();
        int cnt = s_cnt;
        if (cnt > 1) {
            int mc = cnt < 20 ? cnt : 20;
            for (int e = t; e < 140; e += 128) {
                int m = e / 7, d = e - m * 7;
                ob[e] = (m < mc) ? g_boxes7[scand[m] * 7 + d] : 0.f;
            }
            __syncthreads();
            if (t < 112) {
                int r = t >> 4, c = t & 15;
                float s = sb1v[c];
#pragma unroll
                for (int k = 0; k < MM; k++) s += ob[k * 7 + r] * sw1[k * HH + c];
                h1[t] = fmaxf(s, 0.f);
            }
            __syncthreads();
            if (t < 112) {
                int r = t >> 4, c = t & 15;
                float s = sb2v[c];
#pragma unroll
                for (int k = 0; k < HH; k++) s += h1[(r << 4) + k] * sw2[k * HH + c];
                h2[t] = fmaxf(s, 0.f);
            }
            __syncthreads();
            if (t < 7) {
                float s = sb3v;
#pragma unroll
                for (int k = 0; k < HH; k++) s += h2[(t << 4) + k] * sw3[k];
                if (t >= 3 && t < 6) s = fmaxf(s, 1e-5f);
                out[i * 9 + t] = s;
            }
        }
        __syncthreads();
    }
}

// ---------------- launch ----------------
extern "C" void kernel_launch(void* const* d_in, const int* in_sizes, int n_in,
                              void* d_out, int out_size) {
    const float* pb = (const float*)d_in[0];
    const float* ps = (const float*)d_in[1];
    const int*   pl = (const int*)  d_in[2];
    const float* w1 = (const float*)d_in[3];
    const float* b1 = (const float*)d_in[4];
    const float* w2 = (const float*)d_in[5];
    const float* b2 = (const float*)d_in[6];
    const float* w3 = (const float*)d_in[7];
    const float* b3 = (const float*)d_in[8];
    float* out = (float*)d_out;

    k_rank  <<<64, 128>>>(ps);
    k_prep  <<<32, 128>>>(pb, ps, pl, out);
    k_adj   <<<128, 1024>>>();
    k_fix   <<<1, 128>>>();
    k_merge <<<256, 128>>>(w1, b1, w2, b2, w3, b3, out);
}

// round 14
// speedup vs baseline: 1.4597x; 1.4597x over previous
#include <cuda_runtime.h>
#include <math.h>

#define NBOX 4096
#define WORDS 128   // NBOX/32
#define MM 20
#define HH 16
#define NLAB 4

// ---------------- device scratch (all start zero; every launch leaves them zero) ----------------
__device__ float          g_boxes7[NBOX * 7];
__device__ float4         g_bev4[NBOX];
__device__ int            g_lab[NBOX];
__device__ unsigned int   g_sup0[WORDS];              // invalid bits   (cleared in k_fix)
__device__ unsigned int   g_labmask[NLAB * WORDS];    //                (cleared in k_fix)
__device__ unsigned int   g_rows[NBOX * WORDS];       // only deg>31 rows valid
__device__ unsigned short g_pool[NBOX * 31];          // upper (j>i) neighbor lists, ascending
__device__ unsigned int   g_ofsdeg[NBOX];             // ofs(24) | min(deg,255)(8)
__device__ unsigned int   g_poolcnt;                  //                (cleared in k_fix)
__device__ unsigned short g_lolist4[NBOX * 4];        // first 4 reverse neighbors
__device__ unsigned short g_lolist[NBOX * 64];        // reverse overflow (pos 4..63)
__device__ int            g_deglo[NBOX];              //                (cleared in k_fix)
__device__ int            g_suppr[NBOX];              // min kept smaller neighbor, -1 none
__device__ unsigned int   g_keep[WORDS];              // full overwrite in k_fix
__device__ int            g_mtask[NBOX];
__device__ int            g_nmt;                      // full overwrite in k_fix

__device__ __forceinline__ unsigned sort_key(float sc) {
    float f = (sc > 0.2f) ? sc : __int_as_float(0xff800000);
    unsigned b = __float_as_uint(f);
    unsigned u = (b & 0x80000000u) ? ~b : (b | 0x80000000u);
    return ~u;   // ascending == score descending
}

__device__ __forceinline__ float iou_of(float4 a, float aa, float4 bb) {
    float xmin = fmaxf(a.x, bb.x), ymin = fmaxf(a.y, bb.y);
    float xmax = fminf(a.z, bb.z), ymax = fminf(a.w, bb.w);
    float inter = fmaxf(xmax - xmin, 0.f) * fmaxf(ymax - ymin, 0.f);
    float ab = (bb.z - bb.x) * (bb.w - bb.y);
    return inter / fmaxf(aa + ab - inter, 1e-6f);
}

// ---------------- kernel 1: fused rank sort + prep scatter ----------------
__global__ void __launch_bounds__(128) k_rankprep(
    const float* __restrict__ pb, const float* __restrict__ ps,
    const int* __restrict__ pl, float* __restrict__ out) {
    __shared__ unsigned sk[NBOX];       // 16 KB: full key table
    int t = threadIdx.x;
    for (int k = t; k < NBOX; k += 128) sk[k] = sort_key(ps[k]);
    __syncthreads();

    int o = blockIdx.x * 128 + t;       // original index
    unsigned ki = sk[o];
    int rank = 0;
    const uint4* sk4 = (const uint4*)sk;
#pragma unroll 4
    for (int j4 = 0; j4 < NBOX / 4; j4++) {
        uint4 v = sk4[j4];
        int j = j4 * 4;
        rank += (v.x < ki) || (v.x == ki && j + 0 < o);
        rank += (v.y < ki) || (v.y == ki && j + 1 < o);
        rank += (v.z < ki) || (v.z == ki && j + 2 < o);
        rank += (v.w < ki) || (v.w == ki && j + 3 < o);
    }
    int s = rank;                       // sorted position

    float b0 = pb[o*9+0], b1 = pb[o*9+1], b2 = pb[o*9+2];
    float b3 = pb[o*9+3], b4 = pb[o*9+4], b5 = pb[o*9+5];
    float b6 = pb[o*9+6], b7 = pb[o*9+7], b8 = pb[o*9+8];
    g_boxes7[s*7+0] = b0; g_boxes7[s*7+1] = b1; g_boxes7[s*7+2] = b2;
    g_boxes7[s*7+3] = b3; g_boxes7[s*7+4] = b4; g_boxes7[s*7+5] = b5;
    g_boxes7[s*7+6] = b6;
    out[s*9+0] = b0; out[s*9+1] = b1; out[s*9+2] = b2;
    out[s*9+3] = b3; out[s*9+4] = b4; out[s*9+5] = b5;
    out[s*9+6] = b6; out[s*9+7] = b7; out[s*9+8] = b8;

    const float PI = 3.14159265358979323846f;
    float ang = b6 - floorf(b6 / PI + 0.5f) * PI;
    bool sw = fabsf(ang) >= 0.25f * PI;
    float dx = sw ? b4 : b3;
    float dy = sw ? b3 : b4;
    g_bev4[s] = make_float4(b0 - dx * 0.5f, b1 - dy * 0.5f, b0 + dx * 0.5f, b1 + dy * 0.5f);

    int lab = pl[o];
    g_lab[s] = lab;
    float sc = ps[o];
    out[NBOX*9  + s] = sc;
    out[NBOX*10 + s] = (float)lab;

    if (!(sc > 0.2f)) atomicOr(&g_sup0[s >> 5], 1u << (s & 31));   // arrays pre-zeroed
    atomicOr(&g_labmask[lab * WORDS + (s >> 5)], 1u << (s & 31));
}

// ---------------- kernel 2: adjacency + upper lists + reverse appends ----------------
__global__ void __launch_bounds__(1024) k_adj() {
    __shared__ float4 sb[1024];
    __shared__ float  sa[1024];
    __shared__ float4 rb[32];
    __shared__ int    rl[32];
    int t = threadIdx.x;
    int R = blockIdx.x * 32;
    if (t < 32) { rb[t] = g_bev4[R + t]; rl[t] = g_lab[R + t]; }
    __syncthreads();
    int rloc = t >> 5;
    int r = R + rloc;
    int wl = t & 31;
    float4 a = rb[rloc];
    int la = rl[rloc];
    float aa = (a.z - a.x) * (a.w - a.y);
    int w0 = blockIdx.x;
    int T0 = w0 >> 5;

    unsigned mw[4] = {0, 0, 0, 0};
#pragma unroll
    for (int T = 0; T < 4; T++) {
        if (T >= T0) {
            float4 bb0 = g_bev4[T * 1024 + t];
            sb[t] = bb0;
            sa[t] = (bb0.z - bb0.x) * (bb0.w - bb0.y);
            __syncthreads();
            int w = T * 32 + wl;
            unsigned m = 0;
            if (w >= w0) {
                unsigned cand = g_labmask[la * WORDS + w];
                if (w == w0) cand &= 0xffffffffu << (r & 31);
                while (cand) {
                    int b = __ffs(cand) - 1; cand &= cand - 1;
                    int jj = wl * 32 + b;
                    if (iou_of(a, aa, sb[jj]) > 0.3f) m |= 1u << b;
                }
            }
            mw[T] = m;
            __syncthreads();
        }
    }

    int excl[4], tbase[4];
    int running = 0;
#pragma unroll
    for (int T = 0; T < 4; T++) {
        int pc = __popc(mw[T]);
        int incl = pc;
        for (int d = 1; d < 32; d <<= 1) {
            int n = __shfl_up_sync(0xffffffffu, incl, d);
            if (wl >= d) incl += n;
        }
        excl[T] = incl - pc;
        tbase[T] = running;
        running += __shfl_sync(0xffffffffu, incl, 31);
    }
    int deg = running - 1;            // diag always set
    int cap = deg < 31 ? deg : 31;

    unsigned base = 0;
    if (wl == 0 && deg > 0) base = atomicAdd(&g_poolcnt, (unsigned)cap);
    base = __shfl_sync(0xffffffffu, base, 0);

#pragma unroll
    for (int T = 0; T < 4; T++) {
        unsigned v = mw[T];
        int rank0 = tbase[T] + excl[T];   // diag is rank 0
        int wword = T * 32 + wl;
        while (v) {
            int b = __ffs(v) - 1; v &= v - 1;
            int j = wword * 32 + b;
            if (rank0 > 0) {
                if (rank0 - 1 < 31)
                    g_pool[base + rank0 - 1] = (unsigned short)j;
                int pos = atomicAdd(&g_deglo[j], 1);     // reverse edge j <- r
                if (pos < 4) g_lolist4[j * 4 + pos] = (unsigned short)r;
                else if (pos < 64) g_lolist[j * 64 + pos] = (unsigned short)r;
            }
            rank0++;
        }
    }
    if (wl == 0)
        g_ofsdeg[r] = base | ((unsigned)(deg > 255 ? 255 : deg) << 24);

    if (deg > 31) {
        g_rows[r * WORDS +       wl] = mw[0];
        g_rows[r * WORDS +  32 + wl] = mw[1];
        g_rows[r * WORDS +  64 + wl] = mw[2];
        g_rows[r * WORDS +  96 + wl] = mw[3];
    }
}

// ---------------- kernel 3: 1024-thread Jacobi fixpoint (1 barrier/sweep) + cleanup ----------------
__global__ void __launch_bounds__(1024) k_fix() {
    __shared__ unsigned char status[NBOX];      // 0 unknown, 1 kept, 2 not-kept
    __shared__ unsigned char sdeglo[NBOX];
    __shared__ unsigned short slo4[NBOX * 4];   // 32 KB inline reverse lists
    __shared__ unsigned ssup0[WORDS];
    __shared__ unsigned skeep[WORDS];
    __shared__ int s_nmt;
    int t = threadIdx.x;

    if (t < WORDS) { ssup0[t] = g_sup0[t]; g_sup0[t] = 0; skeep[t] = 0; }
    if (t == 0) { s_nmt = 0; g_poolcnt = 0; }
    for (int k = t; k < NLAB * WORDS; k += 1024) g_labmask[k] = 0;
    for (int k = t; k < NBOX; k += 1024) {
        int n = g_deglo[k];
        sdeglo[k] = (unsigned char)(n > 255 ? 255 : n);
        g_deglo[k] = 0;
    }
    for (int k = t; k < NBOX / 2; k += 1024)    // 2048 uint4 = 32 KB
        ((uint4*)slo4)[k] = ((const uint4*)g_lolist4)[k];
    __syncthreads();

    int j0 = t * 4;                             // thread owns 4 contiguous boxes
    unsigned nib = (ssup0[t >> 3] >> ((t & 7) * 4)) & 0xF;  // invalid nibble
    unsigned unres = (~nib) & 0xF;
#pragma unroll
    for (int b = 0; b < 4; b++)
        status[j0 + b] = ((nib >> b) & 1u) ? 2 : 0;
    __syncthreads();

    while (__syncthreads_or(unres != 0)) {
#pragma unroll
        for (int b = 0; b < 4; b++) {
            if (!(unres & (1u << b))) continue;
            int j = j0 + b;
            int n = sdeglo[j];
            int st;
            if (n <= 64) {
                bool anyK = false, allR = true;
                for (int k = 0; k < n; k++) {
                    int u = (k < 4) ? slo4[j * 4 + k] : g_lolist[j * 64 + k];
                    unsigned char s = status[u];
                    anyK |= (s == 1); allR &= (s != 0);
                }
                st = anyK ? 2 : (allR ? 1 : 0);
            } else {
                float4 a = g_bev4[j]; int la = g_lab[j];
                float aa = (a.z - a.x) * (a.w - a.y);
                bool anyK = false, allR = true;
                for (int k = 0; k < j; k++) {
                    if (g_lab[k] != la) continue;
                    if (iou_of(a, aa, g_bev4[k]) > 0.3f) {
                        unsigned char s = status[k];
                        anyK |= (s == 1); allR &= (s != 0);
                    }
                }
                st = anyK ? 2 : (allR ? 1 : 0);
            }
            if (st) { status[j] = (unsigned char)st; unres &= ~(1u << b); }
        }
    }

    // suppressor + keep + merge-task compaction (4 boxes/thread)
#pragma unroll
    for (int b = 0; b < 4; b++) {
        int j = j0 + b;
        unsigned char stj = status[j];
        int sup = -1;
        if (stj == 2 && !((nib >> b) & 1u)) {
            int n = sdeglo[j];
            int mn = 0x7fffffff;
            if (n <= 64) {
                for (int k = 0; k < n; k++) {
                    int u = (k < 4) ? slo4[j * 4 + k] : g_lolist[j * 64 + k];
                    if (status[u] == 1 && u < mn) mn = u;
                }
            } else {
                float4 a = g_bev4[j]; int la = g_lab[j];
                float aa = (a.z - a.x) * (a.w - a.y);
                for (int k = 0; k < j; k++) {
                    if (g_lab[k] != la || status[k] != 1) continue;
                    if (iou_of(a, aa, g_bev4[k]) > 0.3f) { mn = k; break; }
                }
            }
            sup = mn;
        }
        g_suppr[j] = sup;
        if (stj == 1) {
            atomicOr(&skeep[t >> 3], 1u << ((t & 7) * 4 + b));
            if ((g_ofsdeg[j] >> 24) > 0)
                g_mtask[atomicAdd(&s_nmt, 1)] = j;
        }
    }
    __syncthreads();
    if (t < WORDS) g_keep[t] = skeep[t];
    if (t == 0) g_nmt = s_nmt;
}

// ---------------- kernel 4: parallel merge MLP + keep flags ----------------
__global__ void __launch_bounds__(128) k_merge(
    const float* __restrict__ w1, const float* __restrict__ b1,
    const float* __restrict__ w2, const float* __restrict__ b2,
    const float* __restrict__ w3, const float* __restrict__ b3,
    float* __restrict__ out) {
    __shared__ float ob[140];
    __shared__ float h1[112], h2[112];
    __shared__ float sw1[320], sw2[256], sw3[16], sb1v[16], sb2v[16];
    __shared__ float sb3v;
    __shared__ int scand[20];
    __shared__ int s_cnt;
    int t = threadIdx.x;

    if (blockIdx.x < 32) {
        int s = blockIdx.x * 128 + t;
        out[NBOX * 11 + s] = ((g_keep[s >> 5] >> (s & 31)) & 1u) ? 1.0f : 0.0f;
    }

    for (int k = t; k < 320; k += 128) sw1[k] = w1[k];
    for (int k = t; k < 256; k += 128) sw2[k] = w2[k];
    if (t < 16) { sw3[t] = w3[t]; sb1v[t] = b1[t]; sb2v[t] = b2[t]; }
    if (t == 0) sb3v = b3[0];
    __syncthreads();

    int nm = g_nmt;
    for (int task = blockIdx.x; task < nm; task += gridDim.x) {
        int i = g_mtask[task];
        unsigned od = g_ofsdeg[i];
        int deg = od >> 24;

        if (t < 32) {
            if (deg <= 31) {
                bool sel = false; int j = 0;
                if (t < deg) {
                    j = (int)g_pool[(od & 0xffffff) + t];
                    sel = (g_suppr[j] == i);
                }
                unsigned m = __ballot_sync(0xffffffffu, sel);
                if (t == 0) { s_cnt = __popc(m) + 1; scand[0] = i; }
                if (sel) {
                    int rk = __popc(m & ((1u << t) - 1u));
                    if (rk < 19) scand[1 + rk] = j;
                }
            } else {
                uint4 rv = ((const uint4*)(g_rows + (size_t)i * WORDS))[t];
                int ww0 = i >> 5;
                unsigned mm[4];
#pragma unroll
                for (int q = 0; q < 4; q++) {
                    int w = t * 4 + q;
                    unsigned v = (q == 0) ? rv.x : (q == 1) ? rv.y : (q == 2) ? rv.z : rv.w;
                    if (w < ww0) v = 0;
                    if (w == ww0) v &= (0xfffffffeu << (i & 31));   // strictly > i
                    unsigned sel = 0;
                    while (v) {
                        int b = __ffs(v) - 1; v &= v - 1;
                        if (g_suppr[w * 32 + b] == i) sel |= 1u << b;
                    }
                    mm[q] = sel;
                }
                int pc = __popc(mm[0]) + __popc(mm[1]) + __popc(mm[2]) + __popc(mm[3]);
                int incl = pc;
                for (int d = 1; d < 32; d <<= 1) {
                    int v = __shfl_up_sync(0xffffffffu, incl, d);
                    if (t >= d) incl += v;
                }
                int total = __shfl_sync(0xffffffffu, incl, 31);
                int start = incl - pc;
#pragma unroll
                for (int q = 0; q < 4; q++) {
                    unsigned v = mm[q];
                    while (v) {
                        int b = __ffs(v) - 1; v &= v - 1;
                        if (start < 19) scand[1 + start] = (t * 4 + q) * 32 + b;
                        start++;
                    }
                }
                if (t == 0) { s_cnt = total + 1; scand[0] = i; }
            }
        }
        __syncthreads();
        int cnt = s_cnt;
        if (cnt > 1) {
            int mc = cnt < 20 ? cnt : 20;
            for (int e = t; e < 140; e += 128) {
                int m = e / 7, d = e - m * 7;
                ob[e] = (m < mc) ? g_boxes7[scand[m] * 7 + d] : 0.f;
            }
            __syncthreads();
            if (t < 112) {
                int r = t >> 4, c = t & 15;
                float s = sb1v[c];
#pragma unroll
                for (int k = 0; k < MM; k++) s += ob[k * 7 + r] * sw1[k * HH + c];
                h1[t] = fmaxf(s, 0.f);
            }
            __syncthreads();
            if (t < 112) {
                int r = t >> 4, c = t & 15;
                float s = sb2v[c];
#pragma unroll
                for (int k = 0; k < HH; k++) s += h1[(r << 4) + k] * sw2[k * HH + c];
                h2[t] = fmaxf(s, 0.f);
            }
            __syncthreads();
            if (t < 7) {
                float s = sb3v;
#pragma unroll
                for (int k = 0; k < HH; k++) s += h2[(t << 4) + k] * sw3[k];
                if (t >= 3 && t < 6) s = fmaxf(s, 1e-5f);
                out[i * 9 + t] = s;
            }
        }
        __syncthreads();
    }
}

// ---------------- launch ----------------
extern "C" void kernel_launch(void* const* d_in, const int* in_sizes, int n_in,
                              void* d_out, int out_size) {
    const float* pb = (const float*)d_in[0];
    const float* ps = (const float*)d_in[1];
    const int*   pl = (const int*)  d_in[2];
    const float* w1 = (const float*)d_in[3];
    const float* b1 = (const float*)d_in[4];
    const float* w2 = (const float*)d_in[5];
    const float* b2 = (const float*)d_in[6];
    const float* w3 = (const float*)d_in[7];
    const float* b3 = (const float*)d_in[8];
    float* out = (float*)d_out;

    k_rankprep <<<32, 128>>>(pb, ps, pl, out);
    k_adj      <<<128, 1024>>>();
    k_fix      <<<1, 1024>>>();
    k_merge    <<<256, 128>>>(w1, b1, w2, b2, w3, b3, out);
}

// round 15
// speedup vs baseline: 1.7400x; 1.1920x over previous
#include <cuda_runtime.h>
#include <math.h>

#define NBOX 4096
#define WORDS 128   // NBOX/32
#define MM 20
#define HH 16
#define NLAB 4
#define RPARTS 4

// ---------------- device scratch (all start zero; every launch leaves them zero) ----------------
__device__ int            g_rankpart[RPARTS * NBOX];
__device__ float          g_boxes7[NBOX * 7];
__device__ float4         g_bev4[NBOX];
__device__ int            g_lab[NBOX];
__device__ unsigned int   g_sup0[WORDS];              // invalid bits   (cleared in k_fix)
__device__ unsigned int   g_labmask[NLAB * WORDS];    //                (cleared in k_fix)
__device__ unsigned int   g_rows[NBOX * WORDS];       // only deg>31 rows valid
__device__ unsigned short g_pool[NBOX * 31];          // upper (j>i) neighbor lists, ascending
__device__ unsigned int   g_ofsdeg[NBOX];             // ofs(24) | min(deg,255)(8)
__device__ unsigned int   g_poolcnt;                  //                (cleared in k_fix)
__device__ unsigned short g_lolist4[NBOX * 4];        // first 4 reverse neighbors
__device__ unsigned short g_lolist[NBOX * 64];        // reverse overflow (pos 4..63)
__device__ int            g_deglo[NBOX];              //                (cleared in k_fix)
__device__ int            g_suppr[NBOX];              // min kept smaller neighbor, -1 none
__device__ unsigned int   g_keep[WORDS];              // full overwrite in k_fix
__device__ int            g_mtask[NBOX];
__device__ int            g_nmt;                      // full overwrite in k_fix

__device__ __forceinline__ unsigned sort_key(float sc) {
    float f = (sc > 0.2f) ? sc : __int_as_float(0xff800000);
    unsigned b = __float_as_uint(f);
    unsigned u = (b & 0x80000000u) ? ~b : (b | 0x80000000u);
    return ~u;   // ascending == score descending
}

__device__ __forceinline__ float iou_of(float4 a, float aa, float4 bb) {
    float xmin = fmaxf(a.x, bb.x), ymin = fmaxf(a.y, bb.y);
    float xmax = fminf(a.z, bb.z), ymax = fminf(a.w, bb.w);
    float inter = fmaxf(xmax - xmin, 0.f) * fmaxf(ymax - ymin, 0.f);
    float ab = (bb.z - bb.x) * (bb.w - bb.y);
    return inter / fmaxf(aa + ab - inter, 1e-6f);
}

// ---------------- kernel 1: 4-way split-j rank sort (128 blocks) ----------------
__global__ void __launch_bounds__(128) k_rank(const float* __restrict__ scores) {
    __shared__ unsigned sk[NBOX / RPARTS];    // 1024 keys = 4 KB
    int t = threadIdx.x;
    int part = blockIdx.x >> 5;               // 0..3
    int jo = part * (NBOX / RPARTS);
    for (int k = t; k < NBOX / RPARTS; k += 128) sk[k] = sort_key(scores[jo + k]);
    __syncthreads();
    int i = (blockIdx.x & 31) * 128 + t;
    unsigned ki = sort_key(scores[i]);
    int rank = 0;
    const uint4* sk4 = (const uint4*)sk;
#pragma unroll 4
    for (int j4 = 0; j4 < NBOX / (4 * RPARTS); j4++) {   // 256 iterations
        uint4 v = sk4[j4];
        int j = jo + j4 * 4;
        rank += (v.x < ki) || (v.x == ki && j + 0 < i);
        rank += (v.y < ki) || (v.y == ki && j + 1 < i);
        rank += (v.z < ki) || (v.z == ki && j + 2 < i);
        rank += (v.w < ki) || (v.w == ki && j + 3 < i);
    }
    g_rankpart[part * NBOX + i] = rank;
}

// ---------------- kernel 2: scatter prep (sums 4 partials) ----------------
__global__ void __launch_bounds__(128) k_prep(
    const float* __restrict__ pb, const float* __restrict__ ps,
    const int* __restrict__ pl, float* __restrict__ out) {
    int o = blockIdx.x * 128 + threadIdx.x;   // original index
    int s = g_rankpart[o] + g_rankpart[NBOX + o]
          + g_rankpart[2 * NBOX + o] + g_rankpart[3 * NBOX + o];

    float b0 = pb[o*9+0], b1 = pb[o*9+1], b2 = pb[o*9+2];
    float b3 = pb[o*9+3], b4 = pb[o*9+4], b5 = pb[o*9+5];
    float b6 = pb[o*9+6], b7 = pb[o*9+7], b8 = pb[o*9+8];
    g_boxes7[s*7+0] = b0; g_boxes7[s*7+1] = b1; g_boxes7[s*7+2] = b2;
    g_boxes7[s*7+3] = b3; g_boxes7[s*7+4] = b4; g_boxes7[s*7+5] = b5;
    g_boxes7[s*7+6] = b6;
    out[s*9+0] = b0; out[s*9+1] = b1; out[s*9+2] = b2;
    out[s*9+3] = b3; out[s*9+4] = b4; out[s*9+5] = b5;
    out[s*9+6] = b6; out[s*9+7] = b7; out[s*9+8] = b8;

    const float PI = 3.14159265358979323846f;
    float ang = b6 - floorf(b6 / PI + 0.5f) * PI;
    bool sw = fabsf(ang) >= 0.25f * PI;
    float dx = sw ? b4 : b3;
    float dy = sw ? b3 : b4;
    g_bev4[s] = make_float4(b0 - dx * 0.5f, b1 - dy * 0.5f, b0 + dx * 0.5f, b1 + dy * 0.5f);

    int lab = pl[o];
    g_lab[s] = lab;
    float sc = ps[o];
    out[NBOX*9  + s] = sc;
    out[NBOX*10 + s] = (float)lab;

    if (!(sc > 0.2f)) atomicOr(&g_sup0[s >> 5], 1u << (s & 31));   // arrays pre-zeroed
    atomicOr(&g_labmask[lab * WORDS + (s >> 5)], 1u << (s & 31));
}

// ---------------- kernel 3: adjacency + upper lists + reverse appends ----------------
__global__ void __launch_bounds__(1024) k_adj() {
    __shared__ float4 sb[1024];
    __shared__ float  sa[1024];
    __shared__ float4 rb[32];
    __shared__ int    rl[32];
    int t = threadIdx.x;
    int R = blockIdx.x * 32;
    if (t < 32) { rb[t] = g_bev4[R + t]; rl[t] = g_lab[R + t]; }
    __syncthreads();
    int rloc = t >> 5;
    int r = R + rloc;
    int wl = t & 31;
    float4 a = rb[rloc];
    int la = rl[rloc];
    float aa = (a.z - a.x) * (a.w - a.y);
    int w0 = blockIdx.x;
    int T0 = w0 >> 5;

    unsigned mw[4] = {0, 0, 0, 0};
#pragma unroll
    for (int T = 0; T < 4; T++) {
        if (T >= T0) {
            float4 bb0 = g_bev4[T * 1024 + t];
            sb[t] = bb0;
            sa[t] = (bb0.z - bb0.x) * (bb0.w - bb0.y);
            __syncthreads();
            int w = T * 32 + wl;
            unsigned m = 0;
            if (w >= w0) {
                unsigned cand = g_labmask[la * WORDS + w];
                if (w == w0) cand &= 0xffffffffu << (r & 31);
                while (cand) {
                    int b = __ffs(cand) - 1; cand &= cand - 1;
                    int jj = wl * 32 + b;
                    if (iou_of(a, aa, sb[jj]) > 0.3f) m |= 1u << b;
                }
            }
            mw[T] = m;
            __syncthreads();
        }
    }

    int excl[4], tbase[4];
    int running = 0;
#pragma unroll
    for (int T = 0; T < 4; T++) {
        int pc = __popc(mw[T]);
        int incl = pc;
        for (int d = 1; d < 32; d <<= 1) {
            int n = __shfl_up_sync(0xffffffffu, incl, d);
            if (wl >= d) incl += n;
        }
        excl[T] = incl - pc;
        tbase[T] = running;
        running += __shfl_sync(0xffffffffu, incl, 31);
    }
    int deg = running - 1;            // diag always set
    int cap = deg < 31 ? deg : 31;

    unsigned base = 0;
    if (wl == 0 && deg > 0) base = atomicAdd(&g_poolcnt, (unsigned)cap);
    base = __shfl_sync(0xffffffffu, base, 0);

#pragma unroll
    for (int T = 0; T < 4; T++) {
        unsigned v = mw[T];
        int rank0 = tbase[T] + excl[T];   // diag is rank 0
        int wword = T * 32 + wl;
        while (v) {
            int b = __ffs(v) - 1; v &= v - 1;
            int j = wword * 32 + b;
            if (rank0 > 0) {
                if (rank0 - 1 < 31)
                    g_pool[base + rank0 - 1] = (unsigned short)j;
                int pos = atomicAdd(&g_deglo[j], 1);     // reverse edge j <- r
                if (pos < 4) g_lolist4[j * 4 + pos] = (unsigned short)r;
                else if (pos < 64) g_lolist[j * 64 + pos] = (unsigned short)r;
            }
            rank0++;
        }
    }
    if (wl == 0)
        g_ofsdeg[r] = base | ((unsigned)(deg > 255 ? 255 : deg) << 24);

    if (deg > 31) {
        g_rows[r * WORDS +       wl] = mw[0];
        g_rows[r * WORDS +  32 + wl] = mw[1];
        g_rows[r * WORDS +  64 + wl] = mw[2];
        g_rows[r * WORDS +  96 + wl] = mw[3];
    }
}

// ---------------- kernel 4: 1024-thread Jacobi fixpoint (1 barrier/sweep) + cleanup ----------------
__global__ void __launch_bounds__(1024) k_fix() {
    __shared__ unsigned char status[NBOX];      // 0 unknown, 1 kept, 2 not-kept
    __shared__ unsigned char sdeglo[NBOX];
    __shared__ unsigned short slo4[NBOX * 4];   // 32 KB inline reverse lists
    __shared__ unsigned ssup0[WORDS];
    __shared__ unsigned skeep[WORDS];
    __shared__ int s_nmt;
    int t = threadIdx.x;

    if (t < WORDS) { ssup0[t] = g_sup0[t]; g_sup0[t] = 0; skeep[t] = 0; }
    if (t == 0) { s_nmt = 0; g_poolcnt = 0; }
    for (int k = t; k < NLAB * WORDS; k += 1024) g_labmask[k] = 0;
    for (int k = t; k < NBOX; k += 1024) {
        int n = g_deglo[k];
        sdeglo[k] = (unsigned char)(n > 255 ? 255 : n);
        g_deglo[k] = 0;
    }
    for (int k = t; k < NBOX / 2; k += 1024)    // 2048 uint4 = 32 KB
        ((uint4*)slo4)[k] = ((const uint4*)g_lolist4)[k];
    __syncthreads();

    int j0 = t * 4;                             // thread owns 4 contiguous boxes
    unsigned nib = (ssup0[t >> 3] >> ((t & 7) * 4)) & 0xF;  // invalid nibble
    unsigned unres = (~nib) & 0xF;
#pragma unroll
    for (int b = 0; b < 4; b++)
        status[j0 + b] = ((nib >> b) & 1u) ? 2 : 0;
    __syncthreads();

    while (__syncthreads_or(unres != 0)) {
#pragma unroll
        for (int b = 0; b < 4; b++) {
            if (!(unres & (1u << b))) continue;
            int j = j0 + b;
            int n = sdeglo[j];
            int st;
            if (n <= 64) {
                bool anyK = false, allR = true;
                for (int k = 0; k < n; k++) {
                    int u = (k < 4) ? slo4[j * 4 + k] : g_lolist[j * 64 + k];
                    unsigned char s = status[u];
                    anyK |= (s == 1); allR &= (s != 0);
                }
                st = anyK ? 2 : (allR ? 1 : 0);
            } else {
                float4 a = g_bev4[j]; int la = g_lab[j];
                float aa = (a.z - a.x) * (a.w - a.y);
                bool anyK = false, allR = true;
                for (int k = 0; k < j; k++) {
                    if (g_lab[k] != la) continue;
                    if (iou_of(a, aa, g_bev4[k]) > 0.3f) {
                        unsigned char s = status[k];
                        anyK |= (s == 1); allR &= (s != 0);
                    }
                }
                st = anyK ? 2 : (allR ? 1 : 0);
            }
            if (st) { status[j] = (unsigned char)st; unres &= ~(1u << b); }
        }
    }

    // suppressor + keep + merge-task compaction (4 boxes/thread)
#pragma unroll
    for (int b = 0; b < 4; b++) {
        int j = j0 + b;
        unsigned char stj = status[j];
        int sup = -1;
        if (stj == 2 && !((nib >> b) & 1u)) {
            int n = sdeglo[j];
            int mn = 0x7fffffff;
            if (n <= 64) {
                for (int k = 0; k < n; k++) {
                    int u = (k < 4) ? slo4[j * 4 + k] : g_lolist[j * 64 + k];
                    if (status[u] == 1 && u < mn) mn = u;
                }
            } else {
                float4 a = g_bev4[j]; int la = g_lab[j];
                float aa = (a.z - a.x) * (a.w - a.y);
                for (int k = 0; k < j; k++) {
                    if (g_lab[k] != la || status[k] != 1) continue;
                    if (iou_of(a, aa, g_bev4[k]) > 0.3f) { mn = k; break; }
                }
            }
            sup = mn;
        }
        g_suppr[j] = sup;
        if (stj == 1) {
            atomicOr(&skeep[t >> 3], 1u << ((t & 7) * 4 + b));
            if ((g_ofsdeg[j] >> 24) > 0)
                g_mtask[atomicAdd(&s_nmt, 1)] = j;
        }
    }
    __syncthreads();
    if (t < WORDS) g_keep[t] = skeep[t];
    if (t == 0) g_nmt = s_nmt;
}

// ---------------- kernel 5: parallel merge MLP + keep flags ----------------
__global__ void __launch_bounds__(128) k_merge(
    const float* __restrict__ w1, const float* __restrict__ b1,
    const float* __restrict__ w2, const float* __restrict__ b2,
    const float* __restrict__ w3, const float* __restrict__ b3,
    float* __restrict__ out) {
    __shared__ float ob[140];
    __shared__ float h1[112], h2[112];
    __shared__ float sw1[320], sw2[256], sw3[16], sb1v[16], sb2v[16];
    __shared__ float sb3v;
    __shared__ int scand[20];
    __shared__ int s_cnt;
    int t = threadIdx.x;

    if (blockIdx.x < 32) {
        int s = blockIdx.x * 128 + t;
        out[NBOX * 11 + s] = ((g_keep[s >> 5] >> (s & 31)) & 1u) ? 1.0f : 0.0f;
    }

    for (int k = t; k < 320; k += 128) sw1[k] = w1[k];
    for (int k = t; k < 256; k += 128) sw2[k] = w2[k];
    if (t < 16) { sw3[t] = w3[t]; sb1v[t] = b1[t]; sb2v[t] = b2[t]; }
    if (t == 0) sb3v = b3[0];
    __syncthreads();

    int nm = g_nmt;
    for (int task = blockIdx.x; task < nm; task += gridDim.x) {
        int i = g_mtask[task];
        unsigned od = g_ofsdeg[i];
        int deg = od >> 24;

        if (t < 32) {
            if (deg <= 31) {
                bool sel = false; int j = 0;
                if (t < deg) {
                    j = (int)g_pool[(od & 0xffffff) + t];
                    sel = (g_suppr[j] == i);
                }
                unsigned m = __ballot_sync(0xffffffffu, sel);
                if (t == 0) { s_cnt = __popc(m) + 1; scand[0] = i; }
                if (sel) {
                    int rk = __popc(m & ((1u << t) - 1u));
                    if (rk < 19) scand[1 + rk] = j;
                }
            } else {
                uint4 rv = ((const uint4*)(g_rows + (size_t)i * WORDS))[t];
                int ww0 = i >> 5;
                unsigned mm[4];
#pragma unroll
                for (int q = 0; q < 4; q++) {
                    int w = t * 4 + q;
                    unsigned v = (q == 0) ? rv.x : (q == 1) ? rv.y : (q == 2) ? rv.z : rv.w;
                    if (w < ww0) v = 0;
                    if (w == ww0) v &= (0xfffffffeu << (i & 31));   // strictly > i
                    unsigned sel = 0;
                    while (v) {
                        int b = __ffs(v) - 1; v &= v - 1;
                        if (g_suppr[w * 32 + b] == i) sel |= 1u << b;
                    }
                    mm[q] = sel;
                }
                int pc = __popc(mm[0]) + __popc(mm[1]) + __popc(mm[2]) + __popc(mm[3]);
                int incl = pc;
                for (int d = 1; d < 32; d <<= 1) {
                    int v = __shfl_up_sync(0xffffffffu, incl, d);
                    if (t >= d) incl += v;
                }
                int total = __shfl_sync(0xffffffffu, incl, 31);
                int start = incl - pc;
#pragma unroll
                for (int q = 0; q < 4; q++) {
                    unsigned v = mm[q];
                    while (v) {
                        int b = __ffs(v) - 1; v &= v - 1;
                        if (start < 19) scand[1 + start] = (t * 4 + q) * 32 + b;
                        start++;
                    }
                }
                if (t == 0) { s_cnt = total + 1; scand[0] = i; }
            }
        }
        __syncthreads();
        int cnt = s_cnt;
        if (cnt > 1) {
            int mc = cnt < 20 ? cnt : 20;
            for (int e = t; e < 140; e += 128) {
                int m = e / 7, d = e - m * 7;
                ob[e] = (m < mc) ? g_boxes7[scand[m] * 7 + d] : 0.f;
            }
            __syncthreads();
            if (t < 112) {
                int r = t >> 4, c = t & 15;
                float s = sb1v[c];
#pragma unroll
                for (int k = 0; k < MM; k++) s += ob[k * 7 + r] * sw1[k * HH + c];
                h1[t] = fmaxf(s, 0.f);
            }
            __syncthreads();
            if (t < 112) {
                int r = t >> 4, c = t & 15;
                float s = sb2v[c];
#pragma unroll
                for (int k = 0; k < HH; k++) s += h1[(r << 4) + k] * sw2[k * HH + c];
                h2[t] = fmaxf(s, 0.f);
            }
            __syncthreads();
            if (t < 7) {
                float s = sb3v;
#pragma unroll
                for (int k = 0; k < HH; k++) s += h2[(t << 4) + k] * sw3[k];
                if (t >= 3 && t < 6) s = fmaxf(s, 1e-5f);
                out[i * 9 + t] = s;
            }
        }
        __syncthreads();
    }
}

// ---------------- launch ----------------
extern "C" void kernel_launch(void* const* d_in, const int* in_sizes, int n_in,
                              void* d_out, int out_size) {
    const float* pb = (const float*)d_in[0];
    const float* ps = (const float*)d_in[1];
    const int*   pl = (const int*)  d_in[2];
    const float* w1 = (const float*)d_in[3];
    const float* b1 = (const float*)d_in[4];
    const float* w2 = (const float*)d_in[5];
    const float* b2 = (const float*)d_in[6];
    const float* w3 = (const float*)d_in[7];
    const float* b3 = (const float*)d_in[8];
    float* out = (float*)d_out;

    k_rank  <<<128, 128>>>(ps);
    k_prep  <<<32, 128>>>(pb, ps, pl, out);
    k_adj   <<<128, 1024>>>();
    k_fix   <<<1, 1024>>>();
    k_merge <<<256, 128>>>(w1, b1, w2, b2, w3, b3, out);
}

// round 16
// speedup vs baseline: 1.8393x; 1.0571x over previous
#include <cuda_runtime.h>
#include <math.h>

#define NBOX 4096
#define WORDS 128   // NBOX/32
#define MM 20
#define HH 16
#define NLAB 4
#define RPARTS 4

// ---------------- device scratch (all start zero; every launch leaves them zero) ----------------
__device__ int            g_rankpart[RPARTS * NBOX];
__device__ float          g_boxes7[NBOX * 7];
__device__ float4         g_bev4[NBOX];
__device__ int            g_lab[NBOX];
__device__ unsigned int   g_sup0[WORDS];              // invalid bits   (cleared in k_fix)
__device__ unsigned int   g_labmask[NLAB * WORDS];    //                (cleared in k_fix)
__device__ unsigned int   g_rows[NBOX * WORDS];       // only deg>31 rows valid
__device__ unsigned short g_pool[NBOX * 31];          // upper (j>i) neighbor lists, ascending
__device__ unsigned int   g_ofsdeg[NBOX];             // ofs(24) | min(deg,255)(8)
__device__ unsigned int   g_poolcnt;                  //                (cleared in k_fix)
__device__ unsigned short g_lolist4[NBOX * 4];        // first 4 reverse neighbors
__device__ unsigned short g_lolist[NBOX * 64];        // reverse overflow (pos 4..63)
__device__ int            g_deglo[NBOX];              //                (cleared in k_fix)
__device__ int            g_suppr[NBOX];              // min kept smaller neighbor, -1 none
__device__ unsigned int   g_keep[WORDS];              // full overwrite in k_fix
__device__ int            g_mtask[NBOX];
__device__ int            g_nmt;                      // full overwrite in k_fix

__device__ __forceinline__ unsigned sort_key(float sc) {
    float f = (sc > 0.2f) ? sc : __int_as_float(0xff800000);
    unsigned b = __float_as_uint(f);
    unsigned u = (b & 0x80000000u) ? ~b : (b | 0x80000000u);
    return ~u;   // ascending == score descending
}

__device__ __forceinline__ float iou_of(float4 a, float aa, float4 bb) {
    float xmin = fmaxf(a.x, bb.x), ymin = fmaxf(a.y, bb.y);
    float xmax = fminf(a.z, bb.z), ymax = fminf(a.w, bb.w);
    float inter = fmaxf(xmax - xmin, 0.f) * fmaxf(ymax - ymin, 0.f);
    float ab = (bb.z - bb.x) * (bb.w - bb.y);
    return inter / fmaxf(aa + ab - inter, 1e-6f);
}

// ---------------- kernel 1: 4-way split-j rank sort (128 blocks) ----------------
__global__ void __launch_bounds__(128) k_rank(const float* __restrict__ scores) {
    __shared__ unsigned sk[NBOX / RPARTS];    // 1024 keys = 4 KB
    int t = threadIdx.x;
    int part = blockIdx.x >> 5;               // 0..3
    int jo = part * (NBOX / RPARTS);
    for (int k = t; k < NBOX / RPARTS; k += 128) sk[k] = sort_key(scores[jo + k]);
    __syncthreads();
    int i = (blockIdx.x & 31) * 128 + t;
    unsigned ki = sort_key(scores[i]);
    int rank = 0;
    const uint4* sk4 = (const uint4*)sk;
#pragma unroll 4
    for (int j4 = 0; j4 < NBOX / (4 * RPARTS); j4++) {   // 256 iterations
        uint4 v = sk4[j4];
        int j = jo + j4 * 4;
        rank += (v.x < ki) || (v.x == ki && j + 0 < i);
        rank += (v.y < ki) || (v.y == ki && j + 1 < i);
        rank += (v.z < ki) || (v.z == ki && j + 2 < i);
        rank += (v.w < ki) || (v.w == ki && j + 3 < i);
    }
    g_rankpart[part * NBOX + i] = rank;
}

// ---------------- kernel 2: scatter prep (sums 4 partials) ----------------
__global__ void __launch_bounds__(128) k_prep(
    const float* __restrict__ pb, const float* __restrict__ ps,
    const int* __restrict__ pl, float* __restrict__ out) {
    int o = blockIdx.x * 128 + threadIdx.x;   // original index
    int s = g_rankpart[o] + g_rankpart[NBOX + o]
          + g_rankpart[2 * NBOX + o] + g_rankpart[3 * NBOX + o];

    float b0 = pb[o*9+0], b1 = pb[o*9+1], b2 = pb[o*9+2];
    float b3 = pb[o*9+3], b4 = pb[o*9+4], b5 = pb[o*9+5];
    float b6 = pb[o*9+6], b7 = pb[o*9+7], b8 = pb[o*9+8];
    g_boxes7[s*7+0] = b0; g_boxes7[s*7+1] = b1; g_boxes7[s*7+2] = b2;
    g_boxes7[s*7+3] = b3; g_boxes7[s*7+4] = b4; g_boxes7[s*7+5] = b5;
    g_boxes7[s*7+6] = b6;
    out[s*9+0] = b0; out[s*9+1] = b1; out[s*9+2] = b2;
    out[s*9+3] = b3; out[s*9+4] = b4; out[s*9+5] = b5;
    out[s*9+6] = b6; out[s*9+7] = b7; out[s*9+8] = b8;

    const float PI = 3.14159265358979323846f;
    float ang = b6 - floorf(b6 / PI + 0.5f) * PI;
    bool sw = fabsf(ang) >= 0.25f * PI;
    float dx = sw ? b4 : b3;
    float dy = sw ? b3 : b4;
    g_bev4[s] = make_float4(b0 - dx * 0.5f, b1 - dy * 0.5f, b0 + dx * 0.5f, b1 + dy * 0.5f);

    int lab = pl[o];
    g_lab[s] = lab;
    float sc = ps[o];
    out[NBOX*9  + s] = sc;
    out[NBOX*10 + s] = (float)lab;

    if (!(sc > 0.2f)) atomicOr(&g_sup0[s >> 5], 1u << (s & 31));   // arrays pre-zeroed
    atomicOr(&g_labmask[lab * WORDS + (s >> 5)], 1u << (s & 31));
}

// ---------------- kernel 3: adjacency + upper lists + reverse appends ----------------
__global__ void __launch_bounds__(1024) k_adj() {
    __shared__ float4 sb[1024];
    __shared__ float  sa[1024];
    __shared__ float4 rb[32];
    __shared__ int    rl[32];
    int t = threadIdx.x;
    int R = blockIdx.x * 32;
    if (t < 32) { rb[t] = g_bev4[R + t]; rl[t] = g_lab[R + t]; }
    __syncthreads();
    int rloc = t >> 5;
    int r = R + rloc;
    int wl = t & 31;
    float4 a = rb[rloc];
    int la = rl[rloc];
    float aa = (a.z - a.x) * (a.w - a.y);
    int w0 = blockIdx.x;
    int T0 = w0 >> 5;

    unsigned mw[4] = {0, 0, 0, 0};
#pragma unroll
    for (int T = 0; T < 4; T++) {
        if (T >= T0) {
            float4 bb0 = g_bev4[T * 1024 + t];
            sb[t] = bb0;
            sa[t] = (bb0.z - bb0.x) * (bb0.w - bb0.y);
            __syncthreads();
            int w = T * 32 + wl;
            unsigned m = 0;
            if (w >= w0) {
                unsigned cand = g_labmask[la * WORDS + w];
                if (w == w0) cand &= 0xffffffffu << (r & 31);
                while (cand) {
                    int b = __ffs(cand) - 1; cand &= cand - 1;
                    int jj = wl * 32 + b;
                    if (iou_of(a, aa, sb[jj]) > 0.3f) m |= 1u << b;
                }
            }
            mw[T] = m;
            __syncthreads();
        }
    }

    int excl[4], tbase[4];
    int running = 0;
#pragma unroll
    for (int T = 0; T < 4; T++) {
        int pc = __popc(mw[T]);
        int incl = pc;
        for (int d = 1; d < 32; d <<= 1) {
            int n = __shfl_up_sync(0xffffffffu, incl, d);
            if (wl >= d) incl += n;
        }
        excl[T] = incl - pc;
        tbase[T] = running;
        running += __shfl_sync(0xffffffffu, incl, 31);
    }
    int deg = running - 1;            // diag always set
    int cap = deg < 31 ? deg : 31;

    unsigned base = 0;
    if (wl == 0 && deg > 0) base = atomicAdd(&g_poolcnt, (unsigned)cap);
    base = __shfl_sync(0xffffffffu, base, 0);

#pragma unroll
    for (int T = 0; T < 4; T++) {
        unsigned v = mw[T];
        int rank0 = tbase[T] + excl[T];   // diag is rank 0
        int wword = T * 32 + wl;
        while (v) {
            int b = __ffs(v) - 1; v &= v - 1;
            int j = wword * 32 + b;
            if (rank0 > 0) {
                if (rank0 - 1 < 31)
                    g_pool[base + rank0 - 1] = (unsigned short)j;
                int pos = atomicAdd(&g_deglo[j], 1);     // reverse edge j <- r
                if (pos < 4) g_lolist4[j * 4 + pos] = (unsigned short)r;
                else if (pos < 64) g_lolist[j * 64 + pos] = (unsigned short)r;
            }
            rank0++;
        }
    }
    if (wl == 0)
        g_ofsdeg[r] = base | ((unsigned)(deg > 255 ? 255 : deg) << 24);

    if (deg > 31) {
        g_rows[r * WORDS +       wl] = mw[0];
        g_rows[r * WORDS +  32 + wl] = mw[1];
        g_rows[r * WORDS +  64 + wl] = mw[2];
        g_rows[r * WORDS +  96 + wl] = mw[3];
    }
}

// ---------------- kernel 4: lock-free spin fixpoint (volatile smem, no sweep barriers) ----------------
__global__ void __launch_bounds__(1024) k_fix() {
    __shared__ unsigned char status[NBOX];      // 0 unknown, 1 kept, 2 not-kept (monotonic)
    __shared__ unsigned char sdeglo[NBOX];
    __shared__ unsigned short slo4[NBOX * 4];   // 32 KB inline reverse lists
    __shared__ unsigned ssup0[WORDS];
    __shared__ unsigned skeep[WORDS];
    __shared__ int s_nmt;
    volatile unsigned char* vst = status;
    int t = threadIdx.x;

    if (t < WORDS) { ssup0[t] = g_sup0[t]; g_sup0[t] = 0; skeep[t] = 0; }
    if (t == 0) { s_nmt = 0; g_poolcnt = 0; }
    for (int k = t; k < NLAB * WORDS; k += 1024) g_labmask[k] = 0;
    for (int k = t; k < NBOX; k += 1024) {
        int n = g_deglo[k];
        sdeglo[k] = (unsigned char)(n > 255 ? 255 : n);
        g_deglo[k] = 0;
    }
    for (int k = t; k < NBOX / 2; k += 1024)    // 2048 uint4 = 32 KB
        ((uint4*)slo4)[k] = ((const uint4*)g_lolist4)[k];
    __syncthreads();

    int j0 = t * 4;                             // thread owns 4 contiguous boxes
    unsigned nib = (ssup0[t >> 3] >> ((t & 7) * 4)) & 0xF;  // invalid nibble
    unsigned unres = (~nib) & 0xF;
#pragma unroll
    for (int b = 0; b < 4; b++)
        status[j0 + b] = ((nib >> b) & 1u) ? 2 : 0;
    __syncthreads();

    // lock-free spin: acyclic deps (j waits only on k<j), monotonic writes -> terminates
    while (unres) {
#pragma unroll
        for (int b = 0; b < 4; b++) {
            if (!(unres & (1u << b))) continue;
            int j = j0 + b;
            int n = sdeglo[j];
            int st;
            if (n <= 64) {
                bool anyK = false, allR = true;
                for (int k = 0; k < n; k++) {
                    int u = (k < 4) ? slo4[j * 4 + k] : g_lolist[j * 64 + k];
                    unsigned char s = vst[u];
                    anyK |= (s == 1); allR &= (s != 0);
                }
                st = anyK ? 2 : (allR ? 1 : 0);
            } else {
                float4 a = g_bev4[j]; int la = g_lab[j];
                float aa = (a.z - a.x) * (a.w - a.y);
                bool anyK = false, allR = true;
                for (int k = 0; k < j; k++) {
                    if (g_lab[k] != la) continue;
                    if (iou_of(a, aa, g_bev4[k]) > 0.3f) {
                        unsigned char s = vst[k];
                        anyK |= (s == 1); allR &= (s != 0);
                    }
                }
                st = anyK ? 2 : (allR ? 1 : 0);
            }
            if (st) { vst[j] = (unsigned char)st; unres &= ~(1u << b); }
        }
    }
    __syncthreads();   // all statuses final before suppressor pass

    // suppressor + keep + merge-task compaction (4 boxes/thread)
#pragma unroll
    for (int b = 0; b < 4; b++) {
        int j = j0 + b;
        unsigned char stj = status[j];
        int sup = -1;
        if (stj == 2 && !((nib >> b) & 1u)) {
            int n = sdeglo[j];
            int mn = 0x7fffffff;
            if (n <= 64) {
                for (int k = 0; k < n; k++) {
                    int u = (k < 4) ? slo4[j * 4 + k] : g_lolist[j * 64 + k];
                    if (status[u] == 1 && u < mn) mn = u;
                }
            } else {
                float4 a = g_bev4[j]; int la = g_lab[j];
                float aa = (a.z - a.x) * (a.w - a.y);
                for (int k = 0; k < j; k++) {
                    if (g_lab[k] != la || status[k] != 1) continue;
                    if (iou_of(a, aa, g_bev4[k]) > 0.3f) { mn = k; break; }
                }
            }
            sup = mn;
        }
        g_suppr[j] = sup;
        if (stj == 1) {
            atomicOr(&skeep[t >> 3], 1u << ((t & 7) * 4 + b));
            if ((g_ofsdeg[j] >> 24) > 0)
                g_mtask[atomicAdd(&s_nmt, 1)] = j;
        }
    }
    __syncthreads();
    if (t < WORDS) g_keep[t] = skeep[t];
    if (t == 0) g_nmt = s_nmt;
}

// ---------------- kernel 5: warp-per-task merge MLP + keep flags ----------------
__global__ void __launch_bounds__(128) k_merge(
    const float* __restrict__ w1, const float* __restrict__ b1,
    const float* __restrict__ w2, const float* __restrict__ b2,
    const float* __restrict__ w3, const float* __restrict__ b3,
    float* __restrict__ out) {
    __shared__ float sw1[320], sw2[256], sw3[16], sb1v[16], sb2v[16];
    __shared__ float sb3v;
    __shared__ float ob[4][140];
    __shared__ float hh[4][112];
    __shared__ int   scand[4][20];
    int t = threadIdx.x;
    int wid = t >> 5;
    int lane = t & 31;

    if (blockIdx.x < 32) {
        int s = blockIdx.x * 128 + t;
        out[NBOX * 11 + s] = ((g_keep[s >> 5] >> (s & 31)) & 1u) ? 1.0f : 0.0f;
    }

    for (int k = t; k < 320; k += 128) sw1[k] = w1[k];
    for (int k = t; k < 256; k += 128) sw2[k] = w2[k];
    if (t < 16) { sw3[t] = w3[t]; sb1v[t] = b1[t]; sb2v[t] = b2[t]; }
    if (t == 0) sb3v = b3[0];
    __syncthreads();

    int nm = g_nmt;
    for (int task = blockIdx.x * 4 + wid; task < nm; task += gridDim.x * 4) {
        int i = g_mtask[task];
        unsigned od = g_ofsdeg[i];
        int deg = od >> 24;
        int cnt;

        if (deg <= 31) {
            bool sel = false; int j = 0;
            if (lane < deg) {
                j = (int)g_pool[(od & 0xffffff) + lane];
                sel = (g_suppr[j] == i);
            }
            unsigned m = __ballot_sync(0xffffffffu, sel);
            cnt = __popc(m) + 1;
            if (lane == 0) scand[wid][0] = i;
            if (sel) {
                int rk = __popc(m & ((1u << lane) - 1u));
                if (rk < 19) scand[wid][1 + rk] = j;
            }
        } else {
            uint4 rv = ((const uint4*)(g_rows + (size_t)i * WORDS))[lane];
            int ww0 = i >> 5;
            unsigned mm[4];
#pragma unroll
            for (int q = 0; q < 4; q++) {
                int w = lane * 4 + q;
                unsigned v = (q == 0) ? rv.x : (q == 1) ? rv.y : (q == 2) ? rv.z : rv.w;
                if (w < ww0) v = 0;
                if (w == ww0) v &= (0xfffffffeu << (i & 31));   // strictly > i
                unsigned sel = 0;
                while (v) {
                    int b = __ffs(v) - 1; v &= v - 1;
                    if (g_suppr[w * 32 + b] == i) sel |= 1u << b;
                }
                mm[q] = sel;
            }
            int pc = __popc(mm[0]) + __popc(mm[1]) + __popc(mm[2]) + __popc(mm[3]);
            int incl = pc;
            for (int d = 1; d < 32; d <<= 1) {
                int v = __shfl_up_sync(0xffffffffu, incl, d);
                if (lane >= d) incl += v;
            }
            int total = __shfl_sync(0xffffffffu, incl, 31);
            int start = incl - pc;
#pragma unroll
            for (int q = 0; q < 4; q++) {
                unsigned v = mm[q];
                while (v) {
                    int b = __ffs(v) - 1; v &= v - 1;
                    if (start < 19) scand[wid][1 + start] = (lane * 4 + q) * 32 + b;
                    start++;
                }
            }
            if (lane == 0) scand[wid][0] = i;
            cnt = total + 1;
        }
        __syncwarp();

        if (cnt > 1) {
            int mc = cnt < 20 ? cnt : 20;
#pragma unroll
            for (int e = lane; e < 140; e += 32) {
                int m = e / 7, d = e - m * 7;
                ob[wid][e] = (m < mc) ? g_boxes7[scand[wid][m] * 7 + d] : 0.f;
            }
            __syncwarp();
            // h1: 112 outputs, lane handles e = lane + 32k
            float h1v[4];
#pragma unroll
            for (int q = 0; q < 4; q++) {
                int e = lane + 32 * q;
                float s = 0.f;
                if (e < 112) {
                    int r = e >> 4, c = e & 15;
                    s = sb1v[c];
#pragma unroll
                    for (int k = 0; k < MM; k++) s += ob[wid][k * 7 + r] * sw1[k * HH + c];
                    s = fmaxf(s, 0.f);
                }
                h1v[q] = s;
            }
            __syncwarp();
#pragma unroll
            for (int q = 0; q < 4; q++) {
                int e = lane + 32 * q;
                if (e < 112) hh[wid][e] = h1v[q];
            }
            __syncwarp();
            // h2 (compute to regs, then overwrite hh)
            float h2v[4];
#pragma unroll
            for (int q = 0; q < 4; q++) {
                int e = lane + 32 * q;
                float s = 0.f;
                if (e < 112) {
                    int r = e >> 4, c = e & 15;
                    s = sb2v[c];
#pragma unroll
                    for (int k = 0; k < HH; k++) s += hh[wid][(r << 4) + k] * sw2[k * HH + c];
                    s = fmaxf(s, 0.f);
                }
                h2v[q] = s;
            }
            __syncwarp();
#pragma unroll
            for (int q = 0; q < 4; q++) {
                int e = lane + 32 * q;
                if (e < 112) hh[wid][e] = h2v[q];
            }
            __syncwarp();
            if (lane < 7) {
                float s = sb3v;
#pragma unroll
                for (int k = 0; k < HH; k++) s += hh[wid][(lane << 4) + k] * sw3[k];
                if (lane >= 3 && lane < 6) s = fmaxf(s, 1e-5f);
                out[i * 9 + lane] = s;
            }
        }
        __syncwarp();
    }
}

// ---------------- launch ----------------
extern "C" void kernel_launch(void* const* d_in, const int* in_sizes, int n_in,
                              void* d_out, int out_size) {
    const float* pb = (const float*)d_in[0];
    const float* ps = (const float*)d_in[1];
    const int*   pl = (const int*)  d_in[2];
    const float* w1 = (const float*)d_in[3];
    const float* b1 = (const float*)d_in[4];
    const float* w2 = (const float*)d_in[5];
    const float* b2 = (const float*)d_in[6];
    const float* w3 = (const float*)d_in[7];
    const float* b3 = (const float*)d_in[8];
    float* out = (float*)d_out;

    k_rank  <<<128, 128>>>(ps);
    k_prep  <<<32, 128>>>(pb, ps, pl, out);
    k_adj   <<<128, 1024>>>();
    k_fix   <<<1, 1024>>>();
    k_merge <<<256, 128>>>(w1, b1, w2, b2, w3, b3, out);
}

// round 17
// speedup vs baseline: 1.9258x; 1.0470x over previous
#include <cuda_runtime.h>
#include <math.h>

#define NBOX 4096
#define WORDS 128   // NBOX/32
#define MM 20
#define HH 16
#define NLAB 4
#define RPARTS 4

// ---------------- device scratch (all start zero; every launch leaves them zero) ----------------
__device__ int            g_rankpart[RPARTS * NBOX];
__device__ float          g_boxes7[NBOX * 7];
__device__ float4         g_bev4[NBOX];
__device__ int            g_lab[NBOX];
__device__ unsigned int   g_sup0[WORDS];              // invalid bits   (cleared in k_merge)
__device__ unsigned int   g_labmask[NLAB * WORDS];    //                (cleared in k_merge)
__device__ unsigned int   g_rows[NBOX * WORDS];       // only deg>31 rows valid
__device__ unsigned short g_pool[NBOX * 31];          // upper (j>i) neighbor lists, ascending
__device__ unsigned int   g_ofsdeg[NBOX];             // ofs(24) | min(deg,255)(8)
__device__ unsigned int   g_poolcnt;                  //                (cleared in k_merge)
__device__ unsigned short g_lolist4[NBOX * 4];        // first 4 reverse neighbors
__device__ unsigned short g_lolist[NBOX * 64];        // reverse overflow (pos 4..63)
__device__ int            g_deglo[NBOX];              //                (cleared in k_merge)
__device__ int            g_suppr[NBOX];              // min kept smaller neighbor, -1 none
__device__ unsigned int   g_keep[WORDS];              // full overwrite in k_fix
__device__ int            g_mtask[NBOX];
__device__ int            g_nmt;                      // full overwrite in k_fix

__device__ __forceinline__ unsigned sort_key(float sc) {
    float f = (sc > 0.2f) ? sc : __int_as_float(0xff800000);
    unsigned b = __float_as_uint(f);
    unsigned u = (b & 0x80000000u) ? ~b : (b | 0x80000000u);
    return ~u;   // ascending == score descending
}

__device__ __forceinline__ float iou_of(float4 a, float aa, float4 bb) {
    float xmin = fmaxf(a.x, bb.x), ymin = fmaxf(a.y, bb.y);
    float xmax = fminf(a.z, bb.z), ymax = fminf(a.w, bb.w);
    float inter = fmaxf(xmax - xmin, 0.f) * fmaxf(ymax - ymin, 0.f);
    float ab = (bb.z - bb.x) * (bb.w - bb.y);
    return inter / fmaxf(aa + ab - inter, 1e-6f);
}

// ---------------- kernel 1: 4-way split-j rank sort (128 blocks) ----------------
__global__ void __launch_bounds__(128) k_rank(const float* __restrict__ scores) {
    __shared__ unsigned sk[NBOX / RPARTS];    // 1024 keys = 4 KB
    int t = threadIdx.x;
    int part = blockIdx.x >> 5;               // 0..3
    int jo = part * (NBOX / RPARTS);
    for (int k = t; k < NBOX / RPARTS; k += 128) sk[k] = sort_key(scores[jo + k]);
    __syncthreads();
    int i = (blockIdx.x & 31) * 128 + t;
    unsigned ki = sort_key(scores[i]);
    int rank = 0;
    const uint4* sk4 = (const uint4*)sk;
#pragma unroll 4
    for (int j4 = 0; j4 < NBOX / (4 * RPARTS); j4++) {   // 256 iterations
        uint4 v = sk4[j4];
        int j = jo + j4 * 4;
        rank += (v.x < ki) || (v.x == ki && j + 0 < i);
        rank += (v.y < ki) || (v.y == ki && j + 1 < i);
        rank += (v.z < ki) || (v.z == ki && j + 2 < i);
        rank += (v.w < ki) || (v.w == ki && j + 3 < i);
    }
    g_rankpart[part * NBOX + i] = rank;
}

// ---------------- kernel 2: scatter prep (sums 4 partials) ----------------
__global__ void __launch_bounds__(128) k_prep(
    const float* __restrict__ pb, const float* __restrict__ ps,
    const int* __restrict__ pl, float* __restrict__ out) {
    int o = blockIdx.x * 128 + threadIdx.x;   // original index
    int s = g_rankpart[o] + g_rankpart[NBOX + o]
          + g_rankpart[2 * NBOX + o] + g_rankpart[3 * NBOX + o];

    float b0 = pb[o*9+0], b1 = pb[o*9+1], b2 = pb[o*9+2];
    float b3 = pb[o*9+3], b4 = pb[o*9+4], b5 = pb[o*9+5];
    float b6 = pb[o*9+6], b7 = pb[o*9+7], b8 = pb[o*9+8];
    g_boxes7[s*7+0] = b0; g_boxes7[s*7+1] = b1; g_boxes7[s*7+2] = b2;
    g_boxes7[s*7+3] = b3; g_boxes7[s*7+4] = b4; g_boxes7[s*7+5] = b5;
    g_boxes7[s*7+6] = b6;
    out[s*9+0] = b0; out[s*9+1] = b1; out[s*9+2] = b2;
    out[s*9+3] = b3; out[s*9+4] = b4; out[s*9+5] = b5;
    out[s*9+6] = b6; out[s*9+7] = b7; out[s*9+8] = b8;

    const float PI = 3.14159265358979323846f;
    float ang = b6 - floorf(b6 / PI + 0.5f) * PI;
    bool sw = fabsf(ang) >= 0.25f * PI;
    float dx = sw ? b4 : b3;
    float dy = sw ? b3 : b4;
    g_bev4[s] = make_float4(b0 - dx * 0.5f, b1 - dy * 0.5f, b0 + dx * 0.5f, b1 + dy * 0.5f);

    int lab = pl[o];
    g_lab[s] = lab;
    float sc = ps[o];
    out[NBOX*9  + s] = sc;
    out[NBOX*10 + s] = (float)lab;

    if (!(sc > 0.2f)) atomicOr(&g_sup0[s >> 5], 1u << (s & 31));   // arrays pre-zeroed
    atomicOr(&g_labmask[lab * WORDS + (s >> 5)], 1u << (s & 31));
}

// ---------------- kernel 3: adjacency + upper lists + reverse appends ----------------
__global__ void __launch_bounds__(1024) k_adj() {
    __shared__ float4 sb[1024];
    __shared__ float  sa[1024];
    __shared__ float4 rb[32];
    __shared__ int    rl[32];
    int t = threadIdx.x;
    int R = blockIdx.x * 32;
    if (t < 32) { rb[t] = g_bev4[R + t]; rl[t] = g_lab[R + t]; }
    __syncthreads();
    int rloc = t >> 5;
    int r = R + rloc;
    int wl = t & 31;
    float4 a = rb[rloc];
    int la = rl[rloc];
    float aa = (a.z - a.x) * (a.w - a.y);
    int w0 = blockIdx.x;
    int T0 = w0 >> 5;

    unsigned mw[4] = {0, 0, 0, 0};
#pragma unroll
    for (int T = 0; T < 4; T++) {
        if (T >= T0) {
            float4 bb0 = g_bev4[T * 1024 + t];
            sb[t] = bb0;
            sa[t] = (bb0.z - bb0.x) * (bb0.w - bb0.y);
            __syncthreads();
            int w = T * 32 + wl;
            unsigned m = 0;
            if (w >= w0) {
                unsigned cand = g_labmask[la * WORDS + w];
                if (w == w0) cand &= 0xffffffffu << (r & 31);
                while (cand) {
                    int b = __ffs(cand) - 1; cand &= cand - 1;
                    int jj = wl * 32 + b;
                    if (iou_of(a, aa, sb[jj]) > 0.3f) m |= 1u << b;
                }
            }
            mw[T] = m;
            __syncthreads();
        }
    }

    int excl[4], tbase[4];
    int running = 0;
#pragma unroll
    for (int T = 0; T < 4; T++) {
        int pc = __popc(mw[T]);
        int incl = pc;
        for (int d = 1; d < 32; d <<= 1) {
            int n = __shfl_up_sync(0xffffffffu, incl, d);
            if (wl >= d) incl += n;
        }
        excl[T] = incl - pc;
        tbase[T] = running;
        running += __shfl_sync(0xffffffffu, incl, 31);
    }
    int deg = running - 1;            // diag always set
    int cap = deg < 31 ? deg : 31;

    unsigned base = 0;
    if (wl == 0 && deg > 0) base = atomicAdd(&g_poolcnt, (unsigned)cap);
    base = __shfl_sync(0xffffffffu, base, 0);

#pragma unroll
    for (int T = 0; T < 4; T++) {
        unsigned v = mw[T];
        int rank0 = tbase[T] + excl[T];   // diag is rank 0
        int wword = T * 32 + wl;
        while (v) {
            int b = __ffs(v) - 1; v &= v - 1;
            int j = wword * 32 + b;
            if (rank0 > 0) {
                if (rank0 - 1 < 31)
                    g_pool[base + rank0 - 1] = (unsigned short)j;
                int pos = atomicAdd(&g_deglo[j], 1);     // reverse edge j <- r
                if (pos < 4) g_lolist4[j * 4 + pos] = (unsigned short)r;
                else if (pos < 64) g_lolist[j * 64 + pos] = (unsigned short)r;
            }
            rank0++;
        }
    }
    if (wl == 0)
        g_ofsdeg[r] = base | ((unsigned)(deg > 255 ? 255 : deg) << 24);

    if (deg > 31) {
        g_rows[r * WORDS +       wl] = mw[0];
        g_rows[r * WORDS +  32 + wl] = mw[1];
        g_rows[r * WORDS +  64 + wl] = mw[2];
        g_rows[r * WORDS +  96 + wl] = mw[3];
    }
}

// ---------------- kernel 4: lock-free spin fixpoint — own data in registers ----------------
__global__ void __launch_bounds__(1024) k_fix() {
    __shared__ unsigned char status[NBOX];      // 0 unknown, 1 kept, 2 not-kept (monotonic)
    __shared__ unsigned ssup0[WORDS];
    __shared__ unsigned skeep[WORDS];
    __shared__ int s_nmt;
    volatile unsigned char* vst = status;
    int t = threadIdx.x;
    int j0 = t * 4;                             // thread owns boxes j0..j0+3

    if (t < WORDS) { ssup0[t] = g_sup0[t]; skeep[t] = 0; }
    if (t == 0) s_nmt = 0;

    // own degrees + inline reverse lists, registers only
    int4 dl = ((const int4*)g_deglo)[t];
    int degs[4] = { dl.x, dl.y, dl.z, dl.w };
    uint4 lA = ((const uint4*)g_lolist4)[t * 2];
    uint4 lB = ((const uint4*)g_lolist4)[t * 2 + 1];
    unsigned lw[8] = { lA.x, lA.y, lA.z, lA.w, lB.x, lB.y, lB.z, lB.w };
    // entry (b,k) = ushort k of box b  ->  lw[b*2 + (k>>1)] >> ((k&1)*16)
    __syncthreads();

    unsigned nib = (ssup0[t >> 3] >> ((t & 7) * 4)) & 0xF;  // invalid nibble
    unsigned unres = (~nib) & 0xF;
#pragma unroll
    for (int b = 0; b < 4; b++)
        status[j0 + b] = ((nib >> b) & 1u) ? 2 : 0;
    __syncthreads();

    // lock-free spin: acyclic deps (j waits only on k<j), monotonic writes -> terminates
    while (unres) {
#pragma unroll
        for (int b = 0; b < 4; b++) {
            if (!(unres & (1u << b))) continue;
            int j = j0 + b;
            int n = degs[b];
            int st;
            if (n <= 64) {
                bool anyK = false, allR = true;
#pragma unroll
                for (int k = 0; k < 4; k++) {
                    if (k < n) {
                        int u = (lw[b * 2 + (k >> 1)] >> ((k & 1) * 16)) & 0xffff;
                        unsigned char s = vst[u];
                        anyK |= (s == 1); allR &= (s != 0);
                    }
                }
                for (int k = 4; k < n; k++) {
                    int u = g_lolist[j * 64 + k];
                    unsigned char s = vst[u];
                    anyK |= (s == 1); allR &= (s != 0);
                }
                st = anyK ? 2 : (allR ? 1 : 0);
            } else {
                float4 a = g_bev4[j]; int la = g_lab[j];
                float aa = (a.z - a.x) * (a.w - a.y);
                bool anyK = false, allR = true;
                for (int k = 0; k < j; k++) {
                    if (g_lab[k] != la) continue;
                    if (iou_of(a, aa, g_bev4[k]) > 0.3f) {
                        unsigned char s = vst[k];
                        anyK |= (s == 1); allR &= (s != 0);
                    }
                }
                st = anyK ? 2 : (allR ? 1 : 0);
            }
            if (st) { vst[j] = (unsigned char)st; unres &= ~(1u << b); }
        }
    }
    __syncthreads();   // all statuses final before suppressor pass

    // suppressor + keep + merge-task compaction (4 boxes/thread, vectorized suppr store)
    int sup4[4];
#pragma unroll
    for (int b = 0; b < 4; b++) {
        int j = j0 + b;
        unsigned char stj = status[j];
        int sup = -1;
        if (stj == 2 && !((nib >> b) & 1u)) {
            int n = degs[b];
            int mn = 0x7fffffff;
            if (n <= 64) {
#pragma unroll
                for (int k = 0; k < 4; k++) {
                    if (k < n) {
                        int u = (lw[b * 2 + (k >> 1)] >> ((k & 1) * 16)) & 0xffff;
                        if (status[u] == 1 && u < mn) mn = u;
                    }
                }
                for (int k = 4; k < n; k++) {
                    int u = g_lolist[j * 64 + k];
                    if (status[u] == 1 && u < mn) mn = u;
                }
            } else {
                float4 a = g_bev4[j]; int la = g_lab[j];
                float aa = (a.z - a.x) * (a.w - a.y);
                for (int k = 0; k < j; k++) {
                    if (g_lab[k] != la || status[k] != 1) continue;
                    if (iou_of(a, aa, g_bev4[k]) > 0.3f) { mn = k; break; }
                }
            }
            sup = mn;
        }
        sup4[b] = sup;
        if (stj == 1) {
            atomicOr(&skeep[t >> 3], 1u << ((t & 7) * 4 + b));
            if ((g_ofsdeg[j] >> 24) > 0)
                g_mtask[atomicAdd(&s_nmt, 1)] = j;
        }
    }
    ((int4*)g_suppr)[t] = make_int4(sup4[0], sup4[1], sup4[2], sup4[3]);
    __syncthreads();
    if (t < WORDS) g_keep[t] = skeep[t];
    if (t == 0) g_nmt = s_nmt;
}

// ---------------- kernel 5: warp-per-task merge MLP + keep flags + scratch cleanup ----------------
__global__ void __launch_bounds__(128) k_merge(
    const float* __restrict__ w1, const float* __restrict__ b1,
    const float* __restrict__ w2, const float* __restrict__ b2,
    const float* __restrict__ w3, const float* __restrict__ b3,
    float* __restrict__ out) {
    __shared__ float sw1[320], sw2[256], sw3[16], sb1v[16], sb2v[16];
    __shared__ float sb3v;
    __shared__ float ob[4][140];
    __shared__ float hh[4][112];
    __shared__ int   scand[4][20];
    int t = threadIdx.x;
    int wid = t >> 5;
    int lane = t & 31;

    if (blockIdx.x < 32) {
        int s = blockIdx.x * 128 + t;
        out[NBOX * 11 + s] = ((g_keep[s >> 5] >> (s & 31)) & 1u) ? 1.0f : 0.0f;
    } else if (blockIdx.x < 64) {
        g_deglo[(blockIdx.x - 32) * 128 + t] = 0;       // cleanup for next replay
    } else if (blockIdx.x == 64) {
        if (t < WORDS) g_sup0[t] = 0;
        if (t == 127) g_poolcnt = 0;
    } else if (blockIdx.x >= 65 && blockIdx.x < 69) {
        g_labmask[(blockIdx.x - 65) * 128 + t] = 0;
    }

    for (int k = t; k < 320; k += 128) sw1[k] = w1[k];
    for (int k = t; k < 256; k += 128) sw2[k] = w2[k];
    if (t < 16) { sw3[t] = w3[t]; sb1v[t] = b1[t]; sb2v[t] = b2[t]; }
    if (t == 0) sb3v = b3[0];
    __syncthreads();

    int nm = g_nmt;
    for (int task = blockIdx.x * 4 + wid; task < nm; task += gridDim.x * 4) {
        int i = g_mtask[task];
        unsigned od = g_ofsdeg[i];
        int deg = od >> 24;
        int cnt;

        if (deg <= 31) {
            bool sel = false; int j = 0;
            if (lane < deg) {
                j = (int)g_pool[(od & 0xffffff) + lane];
                sel = (g_suppr[j] == i);
            }
            unsigned m = __ballot_sync(0xffffffffu, sel);
            cnt = __popc(m) + 1;
            if (lane == 0) scand[wid][0] = i;
            if (sel) {
                int rk = __popc(m & ((1u << lane) - 1u));
                if (rk < 19) scand[wid][1 + rk] = j;
            }
        } else {
            uint4 rv = ((const uint4*)(g_rows + (size_t)i * WORDS))[lane];
            int ww0 = i >> 5;
            unsigned mm[4];
#pragma unroll
            for (int q = 0; q < 4; q++) {
                int w = lane * 4 + q;
                unsigned v = (q == 0) ? rv.x : (q == 1) ? rv.y : (q == 2) ? rv.z : rv.w;
                if (w < ww0) v = 0;
                if (w == ww0) v &= (0xfffffffeu << (i & 31));   // strictly > i
                unsigned sel = 0;
                while (v) {
                    int b = __ffs(v) - 1; v &= v - 1;
                    if (g_suppr[w * 32 + b] == i) sel |= 1u << b;
                }
                mm[q] = sel;
            }
            int pc = __popc(mm[0]) + __popc(mm[1]) + __popc(mm[2]) + __popc(mm[3]);
            int incl = pc;
            for (int d = 1; d < 32; d <<= 1) {
                int v = __shfl_up_sync(0xffffffffu, incl, d);
                if (lane >= d) incl += v;
            }
            int total = __shfl_sync(0xffffffffu, incl, 31);
            int start = incl - pc;
#pragma unroll
            for (int q = 0; q < 4; q++) {
                unsigned v = mm[q];
                while (v) {
                    int b = __ffs(v) - 1; v &= v - 1;
                    if (start < 19) scand[wid][1 + start] = (lane * 4 + q) * 32 + b;
                    start++;
                }
            }
            if (lane == 0) scand[wid][0] = i;
            cnt = total + 1;
        }
        __syncwarp();

        if (cnt > 1) {
            int mc = cnt < 20 ? cnt : 20;
#pragma unroll
            for (int e = lane; e < 140; e += 32) {
                int m = e / 7, d = e - m * 7;
                ob[wid][e] = (m < mc) ? g_boxes7[scand[wid][m] * 7 + d] : 0.f;
            }
            __syncwarp();
            float h1v[4];
#pragma unroll
            for (int q = 0; q < 4; q++) {
                int e = lane + 32 * q;
                float s = 0.f;
                if (e < 112) {
                    int r = e >> 4, c = e & 15;
                    s = sb1v[c];
#pragma unroll
                    for (int k = 0; k < MM; k++) s += ob[wid][k * 7 + r] * sw1[k * HH + c];
                    s = fmaxf(s, 0.f);
                }
                h1v[q] = s;
            }
            __syncwarp();
#pragma unroll
            for (int q = 0; q < 4; q++) {
                int e = lane + 32 * q;
                if (e < 112) hh[wid][e] = h1v[q];
            }
            __syncwarp();
            float h2v[4];
#pragma unroll
            for (int q = 0; q < 4; q++) {
                int e = lane + 32 * q;
                float s = 0.f;
                if (e < 112) {
                    int r = e >> 4, c = e & 15;
                    s = sb2v[c];
#pragma unroll
                    for (int k = 0; k < HH; k++) s += hh[wid][(r << 4) + k] * sw2[k * HH + c];
                    s = fmaxf(s, 0.f);
                }
                h2v[q] = s;
            }
            __syncwarp();
#pragma unroll
            for (int q = 0; q < 4; q++) {
                int e = lane + 32 * q;
                if (e < 112) hh[wid][e] = h2v[q];
            }
            __syncwarp();
            if (lane < 7) {
                float s = sb3v;
#pragma unroll
                for (int k = 0; k < HH; k++) s += hh[wid][(lane << 4) + k] * sw3[k];
                if (lane >= 3 && lane < 6) s = fmaxf(s, 1e-5f);
                out[i * 9 + lane] = s;
            }
        }
        __syncwarp();
    }
}

// ---------------- launch ----------------
extern "C" void kernel_launch(void* const* d_in, const int* in_sizes, int n_in,
                              void* d_out, int out_size) {
    const float* pb = (const float*)d_in[0];
    const float* ps = (const float*)d_in[1];
    const int*   pl = (const int*)  d_in[2];
    const float* w1 = (const float*)d_in[3];
    const float* b1 = (const float*)d_in[4];
    const float* w2 = (const float*)d_in[5];
    const float* b2 = (const float*)d_in[6];
    const float* w3 = (const float*)d_in[7];
    const float* b3 = (const float*)d_in[8];
    float* out = (float*)d_out;

    k_rank  <<<128, 128>>>(ps);
    k_prep  <<<32, 128>>>(pb, ps, pl, out);
    k_adj   <<<128, 1024>>>();
    k_fix   <<<1, 1024>>>();
    k_merge <<<256, 128>>>(w1, b1, w2, b2, w3, b3, out);
}